// round 5
// baseline (speedup 1.0000x reference)
#include <cuda_runtime.h>
#include <cstdint>
#include <cstddef>

// Problem constants
#define TT 512          // sequence length
#define BB 256          // batch
#define HH 128          // hidden
#define G4 512          // 4*H gates
#define I0 24           // layer0 input

// ---------------- static device scratch (allocation-free) ----------------
__device__ float g_gx[2ull * TT * BB * G4];        // [dir][t][b][512]  512 MB
__device__ float g_y0[(size_t)BB * TT * 256];      // [b][t][256]       128 MB
__device__ float g_whh_t[4 * HH * G4];             // [lay*2+dir][k][g] 1 MB
__device__ float g_wih0_t[2 * I0 * G4];            // [dir][i][g]
__device__ float g_wih1_t[256 * 1024];             // [i][dir*512+g]

// ---------------- activations (accurate enough: ~2^-20 rel) ----------------
__device__ __forceinline__ float sigf(float x) {
    return __fdividef(1.0f, 1.0f + __expf(-x));
}
__device__ __forceinline__ float tanhfast(float x) {
    return __fdividef(2.0f, 1.0f + __expf(-2.0f * x)) - 1.0f;
}

// ---------------- weight prep: transposes ----------------
__global__ void prep_weights(const float* __restrict__ whh0f, const float* __restrict__ whh0b,
                             const float* __restrict__ whh1f, const float* __restrict__ whh1b,
                             const float* __restrict__ wih0f, const float* __restrict__ wih0b,
                             const float* __restrict__ wih1f, const float* __restrict__ wih1b) {
    int tid = blockIdx.x * blockDim.x + threadIdx.x;
    int nth = gridDim.x * blockDim.x;
    // whh: [512][128] -> [k][g]
    for (int idx = tid; idx < 4 * HH * G4; idx += nth) {
        int m = idx >> 16;            // which matrix
        int r = idx & 65535;
        int k = r >> 9;
        int g = r & 511;
        const float* w = (m == 0) ? whh0f : (m == 1) ? whh0b : (m == 2) ? whh1f : whh1b;
        g_whh_t[idx] = w[g * HH + k];
    }
    // wih0: [512][24] -> [d][i][g]
    for (int idx = tid; idx < 2 * I0 * G4; idx += nth) {
        int d = idx / (I0 * G4);
        int r = idx % (I0 * G4);
        int i = r >> 9;
        int g = r & 511;
        const float* w = d ? wih0b : wih0f;
        g_wih0_t[idx] = w[g * I0 + i];
    }
    // wih1: [512][256] per dir -> [i][d*512+g]
    for (int idx = tid; idx < 256 * 1024; idx += nth) {
        int i = idx >> 10;
        int n = idx & 1023;
        int d = n >> 9;
        int g = n & 511;
        const float* w = d ? wih1b : wih1f;
        g_wih1_t[idx] = w[g * 256 + i];
    }
}

// ---------------- gx0: x @ Wih0^T + b (both dirs) ----------------
// block: 512 threads, handles 16 (b,t)-rows. grid = 131072/16 = 8192
__global__ __launch_bounds__(512) void gx0_kernel(const float* __restrict__ x,
                                                  const float* __restrict__ b0f,
                                                  const float* __restrict__ b0b) {
    __shared__ float xs[16][I0];
    int tid = threadIdx.x;
    size_t row0 = (size_t)blockIdx.x * 16;
    if (tid < 16 * I0) {
        int rr = tid / I0, ii = tid % I0;
        xs[rr][ii] = x[(row0 + rr) * I0 + ii];
    }
    __syncthreads();
    int g = tid;
    for (int d = 0; d < 2; d++) {
        float w[I0];
#pragma unroll
        for (int i = 0; i < I0; i++) w[i] = g_wih0_t[(d * I0 + i) * G4 + g];
        float bias = (d ? b0b : b0f)[g];
#pragma unroll 4
        for (int rr = 0; rr < 16; rr++) {
            float acc = bias;
#pragma unroll
            for (int i = 0; i < I0; i++) acc = fmaf(w[i], xs[rr][i], acc);
            size_t row = row0 + rr;          // row = b*512 + t
            int b = (int)(row >> 9);
            int t = (int)(row & 511);
            g_gx[(((size_t)d * TT + t) * BB + b) * G4 + g] = acc;
        }
    }
}

// ---------------- gx1: y0 @ Wih1^T + b, SGEMM 131072x1024x256 ----------------
// 128x128 tile, BK=16, 256 threads, 8x8 microtile
__global__ __launch_bounds__(256, 2) void gx1_gemm(const float* __restrict__ A,
                                                   const float* __restrict__ b1f,
                                                   const float* __restrict__ b1b) {
    __shared__ float A_s[16][132];
    __shared__ float B_s[16][128];
    int tid = threadIdx.x;
    int m0 = blockIdx.x * 128;
    int n0 = blockIdx.y * 128;
    int tx = tid & 15, ty = tid >> 4;
    float acc[8][8];
#pragma unroll
    for (int i = 0; i < 8; i++)
#pragma unroll
        for (int j = 0; j < 8; j++) acc[i][j] = 0.0f;

    for (int k0 = 0; k0 < 256; k0 += 16) {
#pragma unroll
        for (int l = 0; l < 2; l++) {
            int lin = tid + l * 256;
            int ar = lin >> 2;
            int ac4 = lin & 3;
            float4 v = *(const float4*)&A[(size_t)(m0 + ar) * 256 + k0 + ac4 * 4];
            A_s[ac4 * 4 + 0][ar] = v.x;
            A_s[ac4 * 4 + 1][ar] = v.y;
            A_s[ac4 * 4 + 2][ar] = v.z;
            A_s[ac4 * 4 + 3][ar] = v.w;
        }
#pragma unroll
        for (int l = 0; l < 2; l++) {
            int lin = tid + l * 256;
            int br = lin >> 5;
            int bc4 = lin & 31;
            *(float4*)&B_s[br][bc4 * 4] =
                *(const float4*)&g_wih1_t[(size_t)(k0 + br) * 1024 + n0 + bc4 * 4];
        }
        __syncthreads();
#pragma unroll
        for (int k = 0; k < 16; k++) {
            float a[8], b[8];
            float4 av0 = *(const float4*)&A_s[k][ty * 8];
            float4 av1 = *(const float4*)&A_s[k][ty * 8 + 4];
            float4 bv0 = *(const float4*)&B_s[k][tx * 8];
            float4 bv1 = *(const float4*)&B_s[k][tx * 8 + 4];
            a[0] = av0.x; a[1] = av0.y; a[2] = av0.z; a[3] = av0.w;
            a[4] = av1.x; a[5] = av1.y; a[6] = av1.z; a[7] = av1.w;
            b[0] = bv0.x; b[1] = bv0.y; b[2] = bv0.z; b[3] = bv0.w;
            b[4] = bv1.x; b[5] = bv1.y; b[6] = bv1.z; b[7] = bv1.w;
#pragma unroll
            for (int i = 0; i < 8; i++)
#pragma unroll
                for (int j = 0; j < 8; j++) acc[i][j] = fmaf(a[i], b[j], acc[i][j]);
        }
        __syncthreads();
    }
    // epilogue: add bias, scatter into g_gx layout [d][t][b][g]
#pragma unroll
    for (int i = 0; i < 8; i++) {
        int m = m0 + ty * 8 + i;        // m = b*512 + t
        int b = m >> 9;
        int t = m & 511;
#pragma unroll
        for (int j = 0; j < 8; j++) {
            int n = n0 + tx * 8 + j;
            int d = n >> 9;
            int g = n & 511;
            float bias = (d ? b1b : b1f)[g];
            g_gx[(((size_t)d * TT + t) * BB + b) * G4 + g] = acc[i][j] + bias;
        }
    }
}

// ---------------- recurrence: persistent over T, Bt=4 batch rows / CTA ----------------
// grid = 128 (2 dirs x 64 tiles), block = 512 (one gate column each)
#define KC 96   // k-rows of Whh_t cached in smem (96*2KB = 192KB)
#define REC_SMEM (KC * G4 * 4 + 512 * 4 + 2048 * 4)

__global__ __launch_bounds__(512) void rec_kernel(const float* __restrict__ gx,
                                                  float* __restrict__ y_out,
                                                  float* __restrict__ hn_out,
                                                  float* __restrict__ cn_out,
                                                  int layer) {
    extern __shared__ float sm[];
    float* Ws = sm;                    // [KC][512]
    float* h_s = sm + KC * G4;         // [4][128]
    float* gates_s = h_s + 512;        // [4 gate types][4 b][128]

    int tid = threadIdx.x;
    int dir = blockIdx.x & 1;
    int tile = blockIdx.x >> 1;
    int b0 = tile * 4;

    const float* whh = g_whh_t + (size_t)(layer * 2 + dir) * HH * G4;

    // prologue: stage first KC rows of Whh_t into smem
    for (int i = tid; i < KC * G4 / 4; i += 512)
        ((float4*)Ws)[i] = ((const float4*)whh)[i];
    h_s[tid] = 0.0f;

    int g = tid;
    int gt = g >> 7;                  // 0=i 1=f 2=g 3=o (warp-uniform)
    int gj = g & 127;
    int ob = tid >> 7;                // owner batch row
    int oj = tid & 127;               // owner hidden unit
    float c = 0.0f, h_own = 0.0f;

    const float* gxd = gx + (size_t)dir * TT * BB * G4;
    __syncthreads();

    for (int step = 0; step < TT; step++) {
        int t = dir ? (TT - 1 - step) : step;
        const float* gxr = gxd + ((size_t)t * BB + b0) * G4;
        float a0 = gxr[g];
        float a1 = gxr[G4 + g];
        float a2 = gxr[2 * G4 + g];
        float a3 = gxr[3 * G4 + g];

        const float4* h4 = (const float4*)h_s;     // [4][32]
        // cached part
#pragma unroll 4
        for (int kb = 0; kb < KC / 4; kb++) {
            float4 v0 = h4[kb], v1 = h4[32 + kb], v2 = h4[64 + kb], v3 = h4[96 + kb];
            float hb0[4] = {v0.x, v0.y, v0.z, v0.w};
            float hb1[4] = {v1.x, v1.y, v1.z, v1.w};
            float hb2[4] = {v2.x, v2.y, v2.z, v2.w};
            float hb3[4] = {v3.x, v3.y, v3.z, v3.w};
#pragma unroll
            for (int jj = 0; jj < 4; jj++) {
                float w = Ws[(4 * kb + jj) * G4 + g];
                a0 = fmaf(w, hb0[jj], a0);
                a1 = fmaf(w, hb1[jj], a1);
                a2 = fmaf(w, hb2[jj], a2);
                a3 = fmaf(w, hb3[jj], a3);
            }
        }
        // uncached tail rows from L2 (constant addresses, stays L2-hot)
#pragma unroll 4
        for (int kb = KC / 4; kb < HH / 4; kb++) {
            float4 v0 = h4[kb], v1 = h4[32 + kb], v2 = h4[64 + kb], v3 = h4[96 + kb];
            float hb0[4] = {v0.x, v0.y, v0.z, v0.w};
            float hb1[4] = {v1.x, v1.y, v1.z, v1.w};
            float hb2[4] = {v2.x, v2.y, v2.z, v2.w};
            float hb3[4] = {v3.x, v3.y, v3.z, v3.w};
#pragma unroll
            for (int jj = 0; jj < 4; jj++) {
                float w = __ldg(&whh[(4 * kb + jj) * G4 + g]);
                a0 = fmaf(w, hb0[jj], a0);
                a1 = fmaf(w, hb1[jj], a1);
                a2 = fmaf(w, hb2[jj], a2);
                a3 = fmaf(w, hb3[jj], a3);
            }
        }

        // activation (warp-uniform branch: gt constant per warp)
        float v0, v1, v2, v3;
        if (gt == 2) {
            v0 = tanhfast(a0); v1 = tanhfast(a1); v2 = tanhfast(a2); v3 = tanhfast(a3);
        } else {
            v0 = sigf(a0); v1 = sigf(a1); v2 = sigf(a2); v3 = sigf(a3);
        }
        gates_s[gt * 512 + 0 * 128 + gj] = v0;
        gates_s[gt * 512 + 1 * 128 + gj] = v1;
        gates_s[gt * 512 + 2 * 128 + gj] = v2;
        gates_s[gt * 512 + 3 * 128 + gj] = v3;
        __syncthreads();

        // owner update: (ob, oj)
        float gi = gates_s[0 * 512 + ob * 128 + oj];
        float gf = gates_s[1 * 512 + ob * 128 + oj];
        float gg = gates_s[2 * 512 + ob * 128 + oj];
        float go = gates_s[3 * 512 + ob * 128 + oj];
        c = gf * c + gi * gg;
        float hh = go * tanhfast(c);
        h_s[ob * 128 + oj] = hh;
        h_own = hh;
        y_out[((size_t)(b0 + ob) * TT + t) * 256 + dir * 128 + oj] = hh;
        __syncthreads();
    }

    // final states -> h_n / c_n rows (layer*2 + dir)
    int rowsel = layer * 2 + dir;
    hn_out[((size_t)rowsel * BB + (b0 + ob)) * HH + oj] = h_own;
    cn_out[((size_t)rowsel * BB + (b0 + ob)) * HH + oj] = c;
}

// ---------------- launcher ----------------
extern "C" void kernel_launch(void* const* d_in, const int* in_sizes, int n_in,
                              void* d_out, int out_size) {
    const float* x    = (const float*)d_in[0];
    const float* wih0f = (const float*)d_in[1];
    const float* whh0f = (const float*)d_in[2];
    const float* b0f   = (const float*)d_in[3];
    const float* wih0b = (const float*)d_in[4];
    const float* whh0b = (const float*)d_in[5];
    const float* b0b   = (const float*)d_in[6];
    const float* wih1f = (const float*)d_in[7];
    const float* whh1f = (const float*)d_in[8];
    const float* b1f   = (const float*)d_in[9];
    const float* wih1b = (const float*)d_in[10];
    const float* whh1b = (const float*)d_in[11];
    const float* b1b   = (const float*)d_in[12];

    float* out = (float*)d_out;
    float* y1  = out;                                        // [256][512][256]
    float* hn  = out + (size_t)BB * TT * 256;                // [4][256][128]
    float* cn  = hn + 4 * BB * HH;                           // [4][256][128]

    float* gx_ptr;
    float* y0_ptr;
    cudaGetSymbolAddress((void**)&gx_ptr, g_gx);
    cudaGetSymbolAddress((void**)&y0_ptr, g_y0);

    static bool attr_set = false;
    if (!attr_set) {
        cudaFuncSetAttribute(rec_kernel, cudaFuncAttributeMaxDynamicSharedMemorySize, REC_SMEM);
        attr_set = true;
    }

    // 1. weight transposes
    prep_weights<<<512, 256>>>(whh0f, whh0b, whh1f, whh1b, wih0f, wih0b, wih1f, wih1b);
    // 2. layer-0 input projection
    gx0_kernel<<<(BB * TT) / 16, 512>>>(x, b0f, b0b);
    // 3. layer-0 recurrence -> g_y0 + h_n/c_n rows 0,1
    rec_kernel<<<128, 512, REC_SMEM>>>(gx_ptr, y0_ptr, hn, cn, 0);
    // 4. layer-1 input projection (big SGEMM)
    {
        dim3 grid((BB * TT) / 128, 1024 / 128);
        gx1_gemm<<<grid, 256>>>(y0_ptr, b1f, b1b);
    }
    // 5. layer-1 recurrence -> y1 + h_n/c_n rows 2,3
    rec_kernel<<<128, 512, REC_SMEM>>>(gx_ptr, y1, hn, cn, 1);
}

// round 8
// speedup vs baseline: 1.2253x; 1.2253x over previous
#include <cuda_runtime.h>
#include <cuda_bf16.h>
#include <cstdint>
#include <cstddef>

// tcgen05 is arch-SPECIFIC (sm_103a): only emit it when the feature target is
// present. The harness also builds a portable compute_103 PTX pass, which must
// compile (it is never executed on the GB300 — the sm_103a cubin is loaded).
#if defined(__CUDA_ARCH_FEAT_SM103_ALL) || defined(__CUDA_ARCH_FEAT_SM100_ALL) || \
    (defined(__CUDA_ARCH_SPECIFIC__) && (__CUDA_ARCH_SPECIFIC__ >= 1000))
#define HAS_TCGEN05 1
#else
#define HAS_TCGEN05 0
#endif

// Problem constants
#define TT 512          // sequence length
#define BB 256          // batch
#define HH 128          // hidden
#define G4 512          // 4*H gates
#define I0 24           // layer0 input

// ---------------- static device scratch (allocation-free) ----------------
__device__ float g_gx[2ull * TT * BB * G4];                       // [dir][t][b][512]
__device__ float g_whh_t[4 * HH * G4];                            // [lay*2+dir][k][g]
__device__ float g_wih0_t[2 * I0 * G4];                           // [dir][i][g]
__device__ __align__(16) __nv_bfloat16 g_a_hi[(size_t)BB * TT * 256]; // y0 hi  [m][k]
__device__ __align__(16) __nv_bfloat16 g_a_lo[(size_t)BB * TT * 256]; // y0 lo
__device__ __align__(16) __nv_bfloat16 g_b_hi[1024 * 256];            // Wih1 hi [n][k]
__device__ __align__(16) __nv_bfloat16 g_b_lo[1024 * 256];            // Wih1 lo

// ---------------- activations ----------------
__device__ __forceinline__ float sigf(float x) {
    return __fdividef(1.0f, 1.0f + __expf(-x));
}
__device__ __forceinline__ float tanhfast(float x) {
    return __fdividef(2.0f, 1.0f + __expf(-2.0f * x)) - 1.0f;
}

// ---------------- PTX helpers (tcgen05 / mbarrier / cp.async) ----------------
__device__ __forceinline__ uint32_t smem_u32(const void* p) {
    uint32_t a;
    asm("{ .reg .u64 t; cvta.to.shared.u64 t, %1; cvt.u32.u64 %0, t; }" : "=r"(a) : "l"(p));
    return a;
}
__device__ __forceinline__ uint32_t elect1() {
    uint32_t p;
    asm volatile("{ .reg .pred p; elect.sync _|p, 0xFFFFFFFF; selp.b32 %0,1,0,p; }" : "=r"(p));
    return p;
}
#define SWZ128(o) ((o) ^ ((((uint32_t)(o)) >> 3) & 0x70))

static constexpr uint64_t DESC_BASE_SW128 =
    (uint64_t(2) << 61) | (uint64_t(1) << 46) | (uint64_t(64) << 32) | (uint64_t(1) << 16);
__device__ __forceinline__ uint64_t mk_desc(uint32_t addr) {
    return DESC_BASE_SW128 | ((uint64_t)(addr >> 4) & 0x3FFF);
}

// idesc: c=F32, a=BF16, b=BF16, M=128, N=128, K-major both
#define IDESC_GX1 0x8200490u

#if HAS_TCGEN05
__device__ __forceinline__ void mma_ss(uint32_t d, uint64_t a, uint64_t b, uint32_t en) {
    asm volatile(
        "{\n\t.reg .pred p;\n\tsetp.ne.u32 p, %5, 0;\n\t"
        "tcgen05.mma.cta_group::1.kind::f16 [%0], %1, %2, %3, {%4,%4,%4,%4}, p;\n\t}"
        :: "r"(d), "l"(a), "l"(b), "r"(IDESC_GX1), "r"(0u), "r"(en) : "memory");
}

#define TC_ALLOC(addr, n) \
    asm volatile("tcgen05.alloc.cta_group::1.sync.aligned.shared::cta.b32 [%0], %1;" \
                 :: "r"(addr), "r"(n) : "memory")
#define TC_DEALLOC(t, n) \
    asm volatile("tcgen05.dealloc.cta_group::1.sync.aligned.b32 %0, %1;" :: "r"(t), "r"(n))
#define TC_RELINQ() \
    asm volatile("tcgen05.relinquish_alloc_permit.cta_group::1.sync.aligned;")
#define TC_COMMIT(mbar) \
    asm volatile("tcgen05.commit.cta_group::1.mbarrier::arrive::one.shared::cluster.b64 [%0];" \
                 :: "r"(mbar) : "memory")
#define TC_FENCE_AFTER()  asm volatile("tcgen05.fence::after_thread_sync;" ::: "memory")
#define TC_FENCE_BEFORE() asm volatile("tcgen05.fence::before_thread_sync;" ::: "memory")
#define TC_WAIT_LD()      asm volatile("tcgen05.wait::ld.sync.aligned;" ::: "memory")

#define TC_LD_X32(r, tadr) \
    asm volatile( \
        "tcgen05.ld.sync.aligned.32x32b.x32.b32 " \
        "{%0, %1, %2, %3, %4, %5, %6, %7, " \
        " %8, %9, %10, %11, %12, %13, %14, %15, " \
        " %16, %17, %18, %19, %20, %21, %22, %23, " \
        " %24, %25, %26, %27, %28, %29, %30, %31}, [%32];" \
        : "=r"((r)[0]),  "=r"((r)[1]),  "=r"((r)[2]),  "=r"((r)[3]), \
          "=r"((r)[4]),  "=r"((r)[5]),  "=r"((r)[6]),  "=r"((r)[7]), \
          "=r"((r)[8]),  "=r"((r)[9]),  "=r"((r)[10]), "=r"((r)[11]), \
          "=r"((r)[12]), "=r"((r)[13]), "=r"((r)[14]), "=r"((r)[15]), \
          "=r"((r)[16]), "=r"((r)[17]), "=r"((r)[18]), "=r"((r)[19]), \
          "=r"((r)[20]), "=r"((r)[21]), "=r"((r)[22]), "=r"((r)[23]), \
          "=r"((r)[24]), "=r"((r)[25]), "=r"((r)[26]), "=r"((r)[27]), \
          "=r"((r)[28]), "=r"((r)[29]), "=r"((r)[30]), "=r"((r)[31]) \
        : "r"(tadr))
#endif  // HAS_TCGEN05

#define MBAR_INIT(mbar, cnt) \
    asm volatile("mbarrier.init.shared.b64 [%0], %1;" :: "r"(mbar), "r"((uint32_t)(cnt)) : "memory")
#define MBAR_WAIT(mbar, par) do { \
    uint32_t _m = (mbar); uint32_t _p = (par); uint32_t _done; \
    asm volatile("{\n\t.reg .pred p;\n\t" \
        "mbarrier.try_wait.parity.acquire.cta.shared::cta.b64 p, [%1], %2;\n\t" \
        "selp.b32 %0, 1, 0, p;\n\t}" : "=r"(_done) : "r"(_m), "r"(_p) : "memory"); \
    if (!_done) { \
        asm volatile("{\n\t.reg .pred P1;\n\t" \
            "WL_%=:\n\t" \
            "mbarrier.try_wait.parity.acquire.cta.shared::cta.b64 P1, [%0], %1, 0x989680;\n\t" \
            "@P1 bra.uni WD_%=;\n\t" \
            "bra.uni WL_%=;\n\t" \
            "WD_%=:\n\t}" :: "r"(_m), "r"(_p) : "memory"); \
    } \
} while (0)

#define CP_ASYNC16(dst, src) \
    asm volatile("cp.async.cg.shared.global [%0], [%1], 16;" :: "r"(dst), "l"(src) : "memory")
#define CP_COMMIT() asm volatile("cp.async.commit_group;" ::: "memory")
#define CP_WAIT0()  asm volatile("cp.async.wait_group 0;" ::: "memory")
#define FENCE_ASYNC() asm volatile("fence.proxy.async.shared::cta;" ::: "memory")

// ---------------- weight prep: transposes + bf16 split of Wih1 ----------------
__global__ void prep_weights(const float* __restrict__ whh0f, const float* __restrict__ whh0b,
                             const float* __restrict__ whh1f, const float* __restrict__ whh1b,
                             const float* __restrict__ wih0f, const float* __restrict__ wih0b,
                             const float* __restrict__ wih1f, const float* __restrict__ wih1b) {
    int tid = blockIdx.x * blockDim.x + threadIdx.x;
    int nth = gridDim.x * blockDim.x;
    // whh: [512][128] -> [k][g]
    for (int idx = tid; idx < 4 * HH * G4; idx += nth) {
        int m = idx >> 16;
        int r = idx & 65535;
        int k = r >> 9;
        int g = r & 511;
        const float* w = (m == 0) ? whh0f : (m == 1) ? whh0b : (m == 2) ? whh1f : whh1b;
        g_whh_t[idx] = w[g * HH + k];
    }
    // wih0: [512][24] -> [d][i][g]
    for (int idx = tid; idx < 2 * I0 * G4; idx += nth) {
        int d = idx / (I0 * G4);
        int r = idx % (I0 * G4);
        int i = r >> 9;
        int g = r & 511;
        const float* w = d ? wih0b : wih0f;
        g_wih0_t[idx] = w[g * I0 + i];
    }
    // wih1 bf16 hi/lo split: [n=d*512+g][k]
    for (int idx = tid; idx < 1024 * 256; idx += nth) {
        int n = idx >> 8;
        int k = idx & 255;
        int d = n >> 9;
        int g = n & 511;
        const float* w = d ? wih1b : wih1f;
        float v = w[g * 256 + k];
        __nv_bfloat16 h = __float2bfloat16(v);
        g_b_hi[idx] = h;
        g_b_lo[idx] = __float2bfloat16(v - __bfloat162float(h));
    }
}

// ---------------- gx0: x @ Wih0^T + b (both dirs) ----------------
__global__ __launch_bounds__(512) void gx0_kernel(const float* __restrict__ x,
                                                  const float* __restrict__ b0f,
                                                  const float* __restrict__ b0b) {
    __shared__ float xs[16][I0];
    int tid = threadIdx.x;
    size_t row0 = (size_t)blockIdx.x * 16;
    if (tid < 16 * I0) {
        int rr = tid / I0, ii = tid % I0;
        xs[rr][ii] = x[(row0 + rr) * I0 + ii];
    }
    __syncthreads();
    int g = tid;
    for (int d = 0; d < 2; d++) {
        float w[I0];
#pragma unroll
        for (int i = 0; i < I0; i++) w[i] = g_wih0_t[(d * I0 + i) * G4 + g];
        float bias = (d ? b0b : b0f)[g];
#pragma unroll 4
        for (int rr = 0; rr < 16; rr++) {
            float acc = bias;
#pragma unroll
            for (int i = 0; i < I0; i++) acc = fmaf(w[i], xs[rr][i], acc);
            size_t row = row0 + rr;          // row = b*512 + t
            int b = (int)(row >> 9);
            int t = (int)(row & 511);
            g_gx[(((size_t)d * TT + t) * BB + b) * G4 + g] = acc;
        }
    }
}

// ---------------- gx1: tcgen05 bf16-split GEMM ----------------
// grid(4, 1024): x = N-chunk of 256, y = M-tile of 128. 128 threads, 2 CTAs/SM.
#define OFF_AH 0
#define OFF_AL 16384
#define OFF_BH 32768
#define OFF_BL 65536
#define OFF_BIAS 98304
#define OFF_TPTR 99328
#define OFF_MBAR 99336
#define GX1_SMEM (99352 + 1024)

__global__ __launch_bounds__(128, 2) void gx1_mma(const float* __restrict__ b1f,
                                                  const float* __restrict__ b1b) {
#if HAS_TCGEN05
    extern __shared__ char smem_raw[];
    uint32_t sb_raw = smem_u32(smem_raw);
    uint32_t sb = (sb_raw + 1023) & ~1023u;
    char* smem = smem_raw + (sb - sb_raw);

    int tid = threadIdx.x;
    int wid = tid >> 5, lid = tid & 31;
    int n0 = blockIdx.x * 256;
    int m0 = blockIdx.y * 128;
    int d = n0 >> 9;
    int g0 = n0 & 511;

    // bias for this N-chunk
    const float* bsrc = d ? b1b : b1f;
    if (tid < 64) {
        float4 v = *(const float4*)&bsrc[g0 + tid * 4];
        *(float4*)(smem + OFF_BIAS + tid * 16) = v;
    }
    if (wid == 0) {
        TC_ALLOC(sb + OFF_TPTR, 256);
        TC_RELINQ();
        if (elect1()) MBAR_INIT(sb + OFF_MBAR, 1);
    }
    __syncthreads();
    uint32_t tmem;
    asm volatile("ld.shared.b32 %0,[%1];" : "=r"(tmem) : "r"(sb + OFF_TPTR));

    const char* Ah = (const char*)g_a_hi;
    const char* Al = (const char*)g_a_lo;
    const char* Bh = (const char*)g_b_hi;
    const char* Bl = (const char*)g_b_lo;

    for (int kc = 0; kc < 4; kc++) {
        if (kc > 0) MBAR_WAIT(sb + OFF_MBAR, (kc - 1) & 1);  // prev chunk's MMAs drained
        // A tiles: 128 rows x 64 bf16 (128B rows), SW128 swizzle
#pragma unroll 2
        for (int u = tid; u < 1024; u += 128) {
            int r = u >> 3, c = u & 7;
            uint32_t off = SWZ128((uint32_t)(r * 128 + c * 16));
            size_t so = ((size_t)(m0 + r) * 256 + kc * 64) * 2 + c * 16;
            CP_ASYNC16(sb + OFF_AH + off, Ah + so);
            CP_ASYNC16(sb + OFF_AL + off, Al + so);
        }
        // B tiles: 256 rows x 64 bf16
#pragma unroll 2
        for (int u = tid; u < 2048; u += 128) {
            int r = u >> 3, c = u & 7;
            uint32_t off = SWZ128((uint32_t)(r * 128 + c * 16));
            size_t so = ((size_t)(n0 + r) * 256 + kc * 64) * 2 + c * 16;
            CP_ASYNC16(sb + OFF_BH + off, Bh + so);
            CP_ASYNC16(sb + OFF_BL + off, Bl + so);
        }
        CP_COMMIT();
        CP_WAIT0();
        __syncthreads();
        FENCE_ASYNC();

        if (wid == 0 && elect1()) {
            uint64_t ah = mk_desc(sb + OFF_AH);
            uint64_t al = mk_desc(sb + OFF_AL);
            uint64_t bh = mk_desc(sb + OFF_BH);
            uint64_t bl = mk_desc(sb + OFF_BL);
            // N split into 2 halves of 128 (B rows 128..255 at +16384B = +1024 desc units)
            // enable_d (accumulate) must be 0 for the FIRST MMA targeting EACH
            // TMEM destination region (kc==0 && ks==0, separately per nh).
#pragma unroll
            for (int nh = 0; nh < 2; nh++) {
                uint32_t dt = tmem + nh * 128;
                uint64_t boff = nh * 1024;
#pragma unroll
                for (int ks = 0; ks < 4; ks++)
                    mma_ss(dt, ah + ks * 2, bh + boff + ks * 2,
                           (kc == 0 && ks == 0) ? 0u : 1u);
#pragma unroll
                for (int ks = 0; ks < 4; ks++) mma_ss(dt, ah + ks * 2, bl + boff + ks * 2, 1);
#pragma unroll
                for (int ks = 0; ks < 4; ks++) mma_ss(dt, al + ks * 2, bh + boff + ks * 2, 1);
            }
            TC_COMMIT(sb + OFF_MBAR);
        }
    }
    MBAR_WAIT(sb + OFF_MBAR, 1);   // 4th completion
    TC_FENCE_AFTER();

    // epilogue: TMEM -> gmem with bias
    int m = m0 + wid * 32 + lid;
    int b = m >> 9, t = m & 511;
    float* orow = g_gx + (((size_t)d * TT + t) * BB + b) * G4 + g0;
    const float* bias = (const float*)(smem + OFF_BIAS);
#pragma unroll
    for (int cc = 0; cc < 8; cc++) {
        uint32_t r[32];
        TC_LD_X32(r, tmem + cc * 32);
        TC_WAIT_LD();
        int jb = cc * 32;
#pragma unroll
        for (int j = 0; j < 32; j += 4) {
            float4 v;
            v.x = __uint_as_float(r[j + 0]) + bias[jb + j + 0];
            v.y = __uint_as_float(r[j + 1]) + bias[jb + j + 1];
            v.z = __uint_as_float(r[j + 2]) + bias[jb + j + 2];
            v.w = __uint_as_float(r[j + 3]) + bias[jb + j + 3];
            *(float4*)&orow[jb + j] = v;
        }
    }
    TC_FENCE_BEFORE();
    __syncthreads();
    if (wid == 0) TC_DEALLOC(tmem, 256);
#else
    // Portable PTX pass only (never executed on sm_103a: cubin is loaded).
    __trap();
#endif
}

// ---------------- recurrence: persistent over T, Bt=4 batch rows / CTA ----------------
#define KC 104   // k-rows of Whh_t cached in smem
#define REC_SMEM (KC * G4 * 4 + 512 * 4 + 2048 * 4)

__global__ __launch_bounds__(512) void rec_kernel(float* __restrict__ y_f32,
                                                  __nv_bfloat16* __restrict__ yh,
                                                  __nv_bfloat16* __restrict__ yl,
                                                  float* __restrict__ hn_out,
                                                  float* __restrict__ cn_out,
                                                  int layer) {
    extern __shared__ float sm[];
    float* Ws = sm;                    // [KC][512]
    float* h_s = sm + KC * G4;         // [4][128]
    float* gates_s = h_s + 512;        // [4 gate types][4 b][128]

    int tid = threadIdx.x;
    int dir = blockIdx.x & 1;
    int tile = blockIdx.x >> 1;
    int b0 = tile * 4;

    const float* whh = g_whh_t + (size_t)(layer * 2 + dir) * HH * G4;
    for (int i = tid; i < KC * G4 / 4; i += 512)
        ((float4*)Ws)[i] = ((const float4*)whh)[i];
    h_s[tid] = 0.0f;

    int g = tid;
    int gt = g >> 7;
    int gj = g & 127;
    int ob = tid >> 7;
    int oj = tid & 127;
    float c = 0.0f, h_own = 0.0f;

    const float* gxd = g_gx + (size_t)dir * TT * BB * G4;
    __syncthreads();

    // prefetch step 0
    int t0 = dir ? (TT - 1) : 0;
    const float* gxr0 = gxd + ((size_t)t0 * BB + b0) * G4;
    float p0 = gxr0[g], p1 = gxr0[G4 + g], p2 = gxr0[2 * G4 + g], p3 = gxr0[3 * G4 + g];

    for (int step = 0; step < TT; step++) {
        int t = dir ? (TT - 1 - step) : step;
        float a0 = p0, a1 = p1, a2 = p2, a3 = p3;
        if (step + 1 < TT) {
            int tn = dir ? (TT - 2 - step) : (step + 1);
            const float* gxrn = gxd + ((size_t)tn * BB + b0) * G4;
            p0 = gxrn[g]; p1 = gxrn[G4 + g]; p2 = gxrn[2 * G4 + g]; p3 = gxrn[3 * G4 + g];
        }

        const float4* h4 = (const float4*)h_s;     // [4][32]
#pragma unroll 4
        for (int kb = 0; kb < KC / 4; kb++) {
            float4 v0 = h4[kb], v1 = h4[32 + kb], v2 = h4[64 + kb], v3 = h4[96 + kb];
            float hb0[4] = {v0.x, v0.y, v0.z, v0.w};
            float hb1[4] = {v1.x, v1.y, v1.z, v1.w};
            float hb2[4] = {v2.x, v2.y, v2.z, v2.w};
            float hb3[4] = {v3.x, v3.y, v3.z, v3.w};
#pragma unroll
            for (int jj = 0; jj < 4; jj++) {
                float w = Ws[(4 * kb + jj) * G4 + g];
                a0 = fmaf(w, hb0[jj], a0);
                a1 = fmaf(w, hb1[jj], a1);
                a2 = fmaf(w, hb2[jj], a2);
                a3 = fmaf(w, hb3[jj], a3);
            }
        }
#pragma unroll 4
        for (int kb = KC / 4; kb < HH / 4; kb++) {
            float4 v0 = h4[kb], v1 = h4[32 + kb], v2 = h4[64 + kb], v3 = h4[96 + kb];
            float hb0[4] = {v0.x, v0.y, v0.z, v0.w};
            float hb1[4] = {v1.x, v1.y, v1.z, v1.w};
            float hb2[4] = {v2.x, v2.y, v2.z, v2.w};
            float hb3[4] = {v3.x, v3.y, v3.z, v3.w};
#pragma unroll
            for (int jj = 0; jj < 4; jj++) {
                float w = __ldg(&whh[(4 * kb + jj) * G4 + g]);
                a0 = fmaf(w, hb0[jj], a0);
                a1 = fmaf(w, hb1[jj], a1);
                a2 = fmaf(w, hb2[jj], a2);
                a3 = fmaf(w, hb3[jj], a3);
            }
        }

        float v0, v1, v2, v3;
        if (gt == 2) {
            v0 = tanhfast(a0); v1 = tanhfast(a1); v2 = tanhfast(a2); v3 = tanhfast(a3);
        } else {
            v0 = sigf(a0); v1 = sigf(a1); v2 = sigf(a2); v3 = sigf(a3);
        }
        gates_s[gt * 512 + 0 * 128 + gj] = v0;
        gates_s[gt * 512 + 1 * 128 + gj] = v1;
        gates_s[gt * 512 + 2 * 128 + gj] = v2;
        gates_s[gt * 512 + 3 * 128 + gj] = v3;
        __syncthreads();

        float gi = gates_s[0 * 512 + ob * 128 + oj];
        float gf = gates_s[1 * 512 + ob * 128 + oj];
        float gg = gates_s[2 * 512 + ob * 128 + oj];
        float go = gates_s[3 * 512 + ob * 128 + oj];
        c = gf * c + gi * gg;
        float hh = go * tanhfast(c);
        h_s[ob * 128 + oj] = hh;
        h_own = hh;
        if (yh) {
            __nv_bfloat16 bh = __float2bfloat16(hh);
            __nv_bfloat16 bl = __float2bfloat16(hh - __bfloat162float(bh));
            size_t mi = ((size_t)(b0 + ob) * TT + t) * 256 + dir * 128 + oj;
            yh[mi] = bh;
            yl[mi] = bl;
        } else {
            y_f32[((size_t)(b0 + ob) * TT + t) * 256 + dir * 128 + oj] = hh;
        }
        __syncthreads();
    }

    int rowsel = layer * 2 + dir;
    hn_out[((size_t)rowsel * BB + (b0 + ob)) * HH + oj] = h_own;
    cn_out[((size_t)rowsel * BB + (b0 + ob)) * HH + oj] = c;
}

// ---------------- launcher ----------------
extern "C" void kernel_launch(void* const* d_in, const int* in_sizes, int n_in,
                              void* d_out, int out_size) {
    const float* x     = (const float*)d_in[0];
    const float* wih0f = (const float*)d_in[1];
    const float* whh0f = (const float*)d_in[2];
    const float* b0f   = (const float*)d_in[3];
    const float* wih0b = (const float*)d_in[4];
    const float* whh0b = (const float*)d_in[5];
    const float* b0b   = (const float*)d_in[6];
    const float* wih1f = (const float*)d_in[7];
    const float* whh1f = (const float*)d_in[8];
    const float* b1f   = (const float*)d_in[9];
    const float* wih1b = (const float*)d_in[10];
    const float* whh1b = (const float*)d_in[11];
    const float* b1b   = (const float*)d_in[12];

    float* out = (float*)d_out;
    float* y1  = out;                              // [256][512][256]
    float* hn  = out + (size_t)BB * TT * 256;      // [4][256][128]
    float* cn  = hn + 4 * BB * HH;                 // [4][256][128]

    __nv_bfloat16* ah_ptr;
    __nv_bfloat16* al_ptr;
    cudaGetSymbolAddress((void**)&ah_ptr, g_a_hi);
    cudaGetSymbolAddress((void**)&al_ptr, g_a_lo);

    cudaFuncSetAttribute(rec_kernel, cudaFuncAttributeMaxDynamicSharedMemorySize, REC_SMEM);
    cudaFuncSetAttribute(gx1_mma, cudaFuncAttributeMaxDynamicSharedMemorySize, GX1_SMEM);

    // 1. weight transposes + bf16 weight split
    prep_weights<<<512, 256>>>(whh0f, whh0b, whh1f, whh1b, wih0f, wih0b, wih1f, wih1b);
    // 2. layer-0 input projection
    gx0_kernel<<<(BB * TT) / 16, 512>>>(x, b0f, b0b);
    // 3. layer-0 recurrence -> bf16 hi/lo y0 + h_n/c_n rows 0,1
    rec_kernel<<<128, 512, REC_SMEM>>>(nullptr, ah_ptr, al_ptr, hn, cn, 0);
    // 4. layer-1 input projection: tcgen05 bf16-split GEMM
    {
        dim3 grid(4, (BB * TT) / 128);
        gx1_mma<<<grid, 128, GX1_SMEM>>>(b1f, b1b);
    }
    // 5. layer-1 recurrence -> y1 + h_n/c_n rows 2,3
    rec_kernel<<<128, 512, REC_SMEM>>>(y1, nullptr, nullptr, hn, cn, 1);
}

// round 9
// speedup vs baseline: 1.7072x; 1.3932x over previous
#include <cuda_runtime.h>
#include <cuda_bf16.h>
#include <cstdint>
#include <cstddef>

// tcgen05 / f32x2 are arch-SPECIFIC (sm_103a): only emit when the feature
// target is present. The harness also builds a portable compute_103 PTX pass,
// which must compile (never executed on the GB300 — the sm_103a cubin loads).
#if defined(__CUDA_ARCH_FEAT_SM103_ALL) || defined(__CUDA_ARCH_FEAT_SM100_ALL) || \
    (defined(__CUDA_ARCH_SPECIFIC__) && (__CUDA_ARCH_SPECIFIC__ >= 1000))
#define HAS_TCGEN05 1
#else
#define HAS_TCGEN05 0
#endif

// Problem constants
#define TT 512          // sequence length
#define BB 256          // batch
#define HH 128          // hidden
#define G4 512          // 4*H gates
#define I0 24           // layer0 input

// ---------------- static device scratch (allocation-free) ----------------
__device__ float g_gx[2ull * TT * BB * G4];                       // [dir][t][b][512]
__device__ float g_whh_t[4 * HH * G4];                            // [lay*2+dir][k][g]
__device__ float g_wih0_t[2 * I0 * G4];                           // [dir][i][g]
__device__ __align__(16) __nv_bfloat16 g_a_hi[(size_t)BB * TT * 256]; // y0 hi  [m][k]
__device__ __align__(16) __nv_bfloat16 g_a_lo[(size_t)BB * TT * 256]; // y0 lo
__device__ __align__(16) __nv_bfloat16 g_b_hi[1024 * 256];            // Wih1 hi [n][k]
__device__ __align__(16) __nv_bfloat16 g_b_lo[1024 * 256];            // Wih1 lo

// ---------------- activations ----------------
__device__ __forceinline__ float sigf(float x) {
    return __fdividef(1.0f, 1.0f + __expf(-x));
}
__device__ __forceinline__ float tanhfast(float x) {
    return __fdividef(2.0f, 1.0f + __expf(-2.0f * x)) - 1.0f;
}

// ---------------- packed fp32x2 helpers ----------------
typedef unsigned long long ull_t;
__device__ __forceinline__ ull_t pack2(float x, float y) {
    ull_t r;
    asm("mov.b64 %0, {%1, %2};" : "=l"(r) : "f"(x), "f"(y));
    return r;
}
__device__ __forceinline__ void unpack2(ull_t v, float& x, float& y) {
    asm("mov.b64 {%0, %1}, %2;" : "=f"(x), "=f"(y) : "l"(v));
}
#if HAS_TCGEN05
#define FMA2(acc, a, b) \
    asm("fma.rn.f32x2 %0, %1, %2, %3;" : "=l"(acc) : "l"(a), "l"(b), "l"(acc))
#else
#define FMA2(acc, a, b) do { \
    float _ax, _ay, _bx, _by, _cx, _cy; \
    unpack2(a, _ax, _ay); unpack2(b, _bx, _by); unpack2(acc, _cx, _cy); \
    acc = pack2(fmaf(_ax, _bx, _cx), fmaf(_ay, _by, _cy)); \
} while (0)
#endif

// ---------------- PTX helpers (tcgen05 / mbarrier / cp.async) ----------------
__device__ __forceinline__ uint32_t smem_u32(const void* p) {
    uint32_t a;
    asm("{ .reg .u64 t; cvta.to.shared.u64 t, %1; cvt.u32.u64 %0, t; }" : "=r"(a) : "l"(p));
    return a;
}
__device__ __forceinline__ uint32_t elect1() {
    uint32_t p;
    asm volatile("{ .reg .pred p; elect.sync _|p, 0xFFFFFFFF; selp.b32 %0,1,0,p; }" : "=r"(p));
    return p;
}
#define SWZ128(o) ((o) ^ ((((uint32_t)(o)) >> 3) & 0x70))

static constexpr uint64_t DESC_BASE_SW128 =
    (uint64_t(2) << 61) | (uint64_t(1) << 46) | (uint64_t(64) << 32) | (uint64_t(1) << 16);
__device__ __forceinline__ uint64_t mk_desc(uint32_t addr) {
    return DESC_BASE_SW128 | ((uint64_t)(addr >> 4) & 0x3FFF);
}

// idesc: c=F32, a=BF16, b=BF16, M=128, N=128, K-major both
#define IDESC_GX1 0x8200490u

#if HAS_TCGEN05
__device__ __forceinline__ void mma_ss(uint32_t d, uint64_t a, uint64_t b, uint32_t en) {
    asm volatile(
        "{\n\t.reg .pred p;\n\tsetp.ne.u32 p, %5, 0;\n\t"
        "tcgen05.mma.cta_group::1.kind::f16 [%0], %1, %2, %3, {%4,%4,%4,%4}, p;\n\t}"
        :: "r"(d), "l"(a), "l"(b), "r"(IDESC_GX1), "r"(0u), "r"(en) : "memory");
}

#define TC_ALLOC(addr, n) \
    asm volatile("tcgen05.alloc.cta_group::1.sync.aligned.shared::cta.b32 [%0], %1;" \
                 :: "r"(addr), "r"(n) : "memory")
#define TC_DEALLOC(t, n) \
    asm volatile("tcgen05.dealloc.cta_group::1.sync.aligned.b32 %0, %1;" :: "r"(t), "r"(n))
#define TC_RELINQ() \
    asm volatile("tcgen05.relinquish_alloc_permit.cta_group::1.sync.aligned;")
#define TC_COMMIT(mbar) \
    asm volatile("tcgen05.commit.cta_group::1.mbarrier::arrive::one.shared::cluster.b64 [%0];" \
                 :: "r"(mbar) : "memory")
#define TC_FENCE_AFTER()  asm volatile("tcgen05.fence::after_thread_sync;" ::: "memory")
#define TC_FENCE_BEFORE() asm volatile("tcgen05.fence::before_thread_sync;" ::: "memory")
#define TC_WAIT_LD()      asm volatile("tcgen05.wait::ld.sync.aligned;" ::: "memory")

#define TC_LD_X32(r, tadr) \
    asm volatile( \
        "tcgen05.ld.sync.aligned.32x32b.x32.b32 " \
        "{%0, %1, %2, %3, %4, %5, %6, %7, " \
        " %8, %9, %10, %11, %12, %13, %14, %15, " \
        " %16, %17, %18, %19, %20, %21, %22, %23, " \
        " %24, %25, %26, %27, %28, %29, %30, %31}, [%32];" \
        : "=r"((r)[0]),  "=r"((r)[1]),  "=r"((r)[2]),  "=r"((r)[3]), \
          "=r"((r)[4]),  "=r"((r)[5]),  "=r"((r)[6]),  "=r"((r)[7]), \
          "=r"((r)[8]),  "=r"((r)[9]),  "=r"((r)[10]), "=r"((r)[11]), \
          "=r"((r)[12]), "=r"((r)[13]), "=r"((r)[14]), "=r"((r)[15]), \
          "=r"((r)[16]), "=r"((r)[17]), "=r"((r)[18]), "=r"((r)[19]), \
          "=r"((r)[20]), "=r"((r)[21]), "=r"((r)[22]), "=r"((r)[23]), \
          "=r"((r)[24]), "=r"((r)[25]), "=r"((r)[26]), "=r"((r)[27]), \
          "=r"((r)[28]), "=r"((r)[29]), "=r"((r)[30]), "=r"((r)[31]) \
        : "r"(tadr))
#endif  // HAS_TCGEN05

#define MBAR_INIT(mbar, cnt) \
    asm volatile("mbarrier.init.shared.b64 [%0], %1;" :: "r"(mbar), "r"((uint32_t)(cnt)) : "memory")
#define MBAR_WAIT(mbar, par) do { \
    uint32_t _m = (mbar); uint32_t _p = (par); uint32_t _done; \
    asm volatile("{\n\t.reg .pred p;\n\t" \
        "mbarrier.try_wait.parity.acquire.cta.shared::cta.b64 p, [%1], %2;\n\t" \
        "selp.b32 %0, 1, 0, p;\n\t}" : "=r"(_done) : "r"(_m), "r"(_p) : "memory"); \
    if (!_done) { \
        asm volatile("{\n\t.reg .pred P1;\n\t" \
            "WL_%=:\n\t" \
            "mbarrier.try_wait.parity.acquire.cta.shared::cta.b64 P1, [%0], %1, 0x989680;\n\t" \
            "@P1 bra.uni WD_%=;\n\t" \
            "bra.uni WL_%=;\n\t" \
            "WD_%=:\n\t}" :: "r"(_m), "r"(_p) : "memory"); \
    } \
} while (0)

#define CP_ASYNC16(dst, src) \
    asm volatile("cp.async.cg.shared.global [%0], [%1], 16;" :: "r"(dst), "l"(src) : "memory")
#define CP_COMMIT() asm volatile("cp.async.commit_group;" ::: "memory")
#define CP_WAIT0()  asm volatile("cp.async.wait_group 0;" ::: "memory")
#define FENCE_ASYNC() asm volatile("fence.proxy.async.shared::cta;" ::: "memory")

// ---------------- weight prep: transposes + bf16 split of Wih1 ----------------
__global__ void prep_weights(const float* __restrict__ whh0f, const float* __restrict__ whh0b,
                             const float* __restrict__ whh1f, const float* __restrict__ whh1b,
                             const float* __restrict__ wih0f, const float* __restrict__ wih0b,
                             const float* __restrict__ wih1f, const float* __restrict__ wih1b) {
    int tid = blockIdx.x * blockDim.x + threadIdx.x;
    int nth = gridDim.x * blockDim.x;
    // whh: [512][128] -> [k][g]
    for (int idx = tid; idx < 4 * HH * G4; idx += nth) {
        int m = idx >> 16;
        int r = idx & 65535;
        int k = r >> 9;
        int g = r & 511;
        const float* w = (m == 0) ? whh0f : (m == 1) ? whh0b : (m == 2) ? whh1f : whh1b;
        g_whh_t[idx] = w[g * HH + k];
    }
    // wih0: [512][24] -> [d][i][g]
    for (int idx = tid; idx < 2 * I0 * G4; idx += nth) {
        int d = idx / (I0 * G4);
        int r = idx % (I0 * G4);
        int i = r >> 9;
        int g = r & 511;
        const float* w = d ? wih0b : wih0f;
        g_wih0_t[idx] = w[g * I0 + i];
    }
    // wih1 bf16 hi/lo split: [n=d*512+g][k]
    for (int idx = tid; idx < 1024 * 256; idx += nth) {
        int n = idx >> 8;
        int k = idx & 255;
        int d = n >> 9;
        int g = n & 511;
        const float* w = d ? wih1b : wih1f;
        float v = w[g * 256 + k];
        __nv_bfloat16 h = __float2bfloat16(v);
        g_b_hi[idx] = h;
        g_b_lo[idx] = __float2bfloat16(v - __bfloat162float(h));
    }
}

// ---------------- gx0: x @ Wih0^T + b (both dirs) ----------------
__global__ __launch_bounds__(512) void gx0_kernel(const float* __restrict__ x,
                                                  const float* __restrict__ b0f,
                                                  const float* __restrict__ b0b) {
    __shared__ float xs[16][I0];
    int tid = threadIdx.x;
    size_t row0 = (size_t)blockIdx.x * 16;
    if (tid < 16 * I0) {
        int rr = tid / I0, ii = tid % I0;
        xs[rr][ii] = x[(row0 + rr) * I0 + ii];
    }
    __syncthreads();
    int g = tid;
    for (int d = 0; d < 2; d++) {
        float w[I0];
#pragma unroll
        for (int i = 0; i < I0; i++) w[i] = g_wih0_t[(d * I0 + i) * G4 + g];
        float bias = (d ? b0b : b0f)[g];
#pragma unroll 4
        for (int rr = 0; rr < 16; rr++) {
            float acc = bias;
#pragma unroll
            for (int i = 0; i < I0; i++) acc = fmaf(w[i], xs[rr][i], acc);
            size_t row = row0 + rr;          // row = b*512 + t
            int b = (int)(row >> 9);
            int t = (int)(row & 511);
            g_gx[(((size_t)d * TT + t) * BB + b) * G4 + g] = acc;
        }
    }
}

// ---------------- gx1: tcgen05 bf16-split GEMM ----------------
// grid(4, 1024): x = N-chunk of 256, y = M-tile of 128. 128 threads, 2 CTAs/SM.
#define OFF_AH 0
#define OFF_AL 16384
#define OFF_BH 32768
#define OFF_BL 65536
#define OFF_BIAS 98304
#define OFF_TPTR 99328
#define OFF_MBAR 99336
#define GX1_SMEM (99352 + 1024)

__global__ __launch_bounds__(128, 2) void gx1_mma(const float* __restrict__ b1f,
                                                  const float* __restrict__ b1b) {
#if HAS_TCGEN05
    extern __shared__ char smem_raw[];
    uint32_t sb_raw = smem_u32(smem_raw);
    uint32_t sb = (sb_raw + 1023) & ~1023u;
    char* smem = smem_raw + (sb - sb_raw);

    int tid = threadIdx.x;
    int wid = tid >> 5, lid = tid & 31;
    int n0 = blockIdx.x * 256;
    int m0 = blockIdx.y * 128;
    int d = n0 >> 9;
    int g0 = n0 & 511;

    // bias for this N-chunk
    const float* bsrc = d ? b1b : b1f;
    if (tid < 64) {
        float4 v = *(const float4*)&bsrc[g0 + tid * 4];
        *(float4*)(smem + OFF_BIAS + tid * 16) = v;
    }
    if (wid == 0) {
        TC_ALLOC(sb + OFF_TPTR, 256);
        TC_RELINQ();
        if (elect1()) MBAR_INIT(sb + OFF_MBAR, 1);
    }
    __syncthreads();
    uint32_t tmem;
    asm volatile("ld.shared.b32 %0,[%1];" : "=r"(tmem) : "r"(sb + OFF_TPTR));

    const char* Ah = (const char*)g_a_hi;
    const char* Al = (const char*)g_a_lo;
    const char* Bh = (const char*)g_b_hi;
    const char* Bl = (const char*)g_b_lo;

    for (int kc = 0; kc < 4; kc++) {
        if (kc > 0) MBAR_WAIT(sb + OFF_MBAR, (kc - 1) & 1);  // prev chunk's MMAs drained
        // A tiles: 128 rows x 64 bf16 (128B rows), SW128 swizzle
#pragma unroll 2
        for (int u = tid; u < 1024; u += 128) {
            int r = u >> 3, c = u & 7;
            uint32_t off = SWZ128((uint32_t)(r * 128 + c * 16));
            size_t so = ((size_t)(m0 + r) * 256 + kc * 64) * 2 + c * 16;
            CP_ASYNC16(sb + OFF_AH + off, Ah + so);
            CP_ASYNC16(sb + OFF_AL + off, Al + so);
        }
        // B tiles: 256 rows x 64 bf16
#pragma unroll 2
        for (int u = tid; u < 2048; u += 128) {
            int r = u >> 3, c = u & 7;
            uint32_t off = SWZ128((uint32_t)(r * 128 + c * 16));
            size_t so = ((size_t)(n0 + r) * 256 + kc * 64) * 2 + c * 16;
            CP_ASYNC16(sb + OFF_BH + off, Bh + so);
            CP_ASYNC16(sb + OFF_BL + off, Bl + so);
        }
        CP_COMMIT();
        CP_WAIT0();
        __syncthreads();
        FENCE_ASYNC();

        if (wid == 0 && elect1()) {
            uint64_t ah = mk_desc(sb + OFF_AH);
            uint64_t al = mk_desc(sb + OFF_AL);
            uint64_t bh = mk_desc(sb + OFF_BH);
            uint64_t bl = mk_desc(sb + OFF_BL);
            // N split into 2 halves of 128 (B rows 128..255 at +16384B = +1024 desc units)
            // enable_d (accumulate) must be 0 for the FIRST MMA targeting EACH
            // TMEM destination region (kc==0 && ks==0, separately per nh).
#pragma unroll
            for (int nh = 0; nh < 2; nh++) {
                uint32_t dt = tmem + nh * 128;
                uint64_t boff = nh * 1024;
#pragma unroll
                for (int ks = 0; ks < 4; ks++)
                    mma_ss(dt, ah + ks * 2, bh + boff + ks * 2,
                           (kc == 0 && ks == 0) ? 0u : 1u);
#pragma unroll
                for (int ks = 0; ks < 4; ks++) mma_ss(dt, ah + ks * 2, bl + boff + ks * 2, 1);
#pragma unroll
                for (int ks = 0; ks < 4; ks++) mma_ss(dt, al + ks * 2, bh + boff + ks * 2, 1);
            }
            TC_COMMIT(sb + OFF_MBAR);
        }
    }
    MBAR_WAIT(sb + OFF_MBAR, 1);   // 4th completion
    TC_FENCE_AFTER();

    // epilogue: TMEM -> gmem with bias
    int m = m0 + wid * 32 + lid;
    int b = m >> 9, t = m & 511;
    float* orow = g_gx + (((size_t)d * TT + t) * BB + b) * G4 + g0;
    const float* bias = (const float*)(smem + OFF_BIAS);
#pragma unroll
    for (int cc = 0; cc < 8; cc++) {
        uint32_t r[32];
        TC_LD_X32(r, tmem + cc * 32);
        TC_WAIT_LD();
        int jb = cc * 32;
#pragma unroll
        for (int j = 0; j < 32; j += 4) {
            float4 v;
            v.x = __uint_as_float(r[j + 0]) + bias[jb + j + 0];
            v.y = __uint_as_float(r[j + 1]) + bias[jb + j + 1];
            v.z = __uint_as_float(r[j + 2]) + bias[jb + j + 2];
            v.w = __uint_as_float(r[j + 3]) + bias[jb + j + 3];
            *(float4*)&orow[jb + j] = v;
        }
    }
    TC_FENCE_BEFORE();
    __syncthreads();
    if (wid == 0) TC_DEALLOC(tmem, 256);
#else
    // Portable PTX pass only (never executed on sm_103a: cubin is loaded).
    __trap();
#endif
}

// ---------------- recurrence: f32x2 packed math, persistent over T ----------------
// grid = 128 (2 dirs x 64 batch tiles of 4), block = 512 (one gate column each).
// Weight rows [0,KR) live in registers (fully unrolled); rows [KR,128) live in
// smem, pre-paired {w[k],w[k+1]} so one LDS.64 feeds 2 k-steps.
#define KR 48                               // k-rows in registers
#define NSP ((HH - KR) / 2)                 // smem k-row PAIRS = 40
#define WP_FLOATS (NSP * G4 * 2)            // 40960 floats = 160 KB
#define REC_SMEM ((WP_FLOATS + 256 + 256 + 2048) * 4)

__global__ __launch_bounds__(512) void rec_kernel(float* __restrict__ y_f32,
                                                  __nv_bfloat16* __restrict__ yh,
                                                  __nv_bfloat16* __restrict__ yl,
                                                  float* __restrict__ hn_out,
                                                  float* __restrict__ cn_out,
                                                  int layer) {
    extern __shared__ float sm[];
    float* Wp = sm;                         // paired weights [NSP][512][2]
    float* hA = sm + WP_FLOATS;             // h for batch 0,1: hA[k*2+b]
    float* hB = hA + 256;                   // h for batch 2,3: hB[k*2+(b-2)]
    float* gates_s = hB + 256;              // [4 gate types][4 b][128]

    int tid = threadIdx.x;
    int dir = blockIdx.x & 1;
    int tile = blockIdx.x >> 1;
    int b0 = tile * 4;

    const float* whh = g_whh_t + (size_t)(layer * 2 + dir) * HH * G4;

    int g = tid;
    int gt = g >> 7;                        // 0=i 1=f 2=g 3=o (warp-uniform)
    int gj = g & 127;
    int ob = tid >> 7;                      // owner batch row
    int oj = tid & 127;                     // owner hidden unit

    // stage paired smem weights: rows [KR, 128)
    for (int i = tid; i < NSP * G4; i += 512) {
        int p = i >> 9, gg = i & 511;
        int k = KR + 2 * p;
        float2 wv = make_float2(whh[(size_t)k * G4 + gg], whh[(size_t)(k + 1) * G4 + gg]);
        *(float2*)&Wp[(size_t)i * 2] = wv;
    }
    // register weights: rows [0, KR)
    float w_r[KR];
#pragma unroll
    for (int i = 0; i < KR; i++) w_r[i] = whh[(size_t)i * G4 + g];

    if (tid < 256) { hA[tid] = 0.0f; hB[tid] = 0.0f; }

    float c = 0.0f, h_own = 0.0f;
    const float* gxd = g_gx + (size_t)dir * TT * BB * G4;
    __syncthreads();

    // prefetch step 0
    int t0 = dir ? (TT - 1) : 0;
    const float* gxr0 = gxd + ((size_t)t0 * BB + b0) * G4;
    float p0 = gxr0[g], p1 = gxr0[G4 + g], p2 = gxr0[2 * G4 + g], p3 = gxr0[3 * G4 + g];

    for (int step = 0; step < TT; step++) {
        int t = dir ? (TT - 1 - step) : step;
        ull_t A01 = pack2(p0, p1);
        ull_t A23 = pack2(p2, p3);
        if (step + 1 < TT) {
            int tn = dir ? (TT - 2 - step) : (step + 1);
            const float* gxrn = gxd + ((size_t)tn * BB + b0) * G4;
            p0 = gxrn[g]; p1 = gxrn[G4 + g]; p2 = gxrn[2 * G4 + g]; p3 = gxrn[3 * G4 + g];
        }

        // register-weight half: k in [0, KR)
#pragma unroll
        for (int i = 0; i < KR / 2; i++) {
            ulonglong2 hva = *(const ulonglong2*)&hA[4 * i];   // {k=2i: b0,b1 | k=2i+1: b0,b1}
            ulonglong2 hvb = *(const ulonglong2*)&hB[4 * i];
            ull_t w0 = pack2(w_r[2 * i], w_r[2 * i]);
            ull_t w1 = pack2(w_r[2 * i + 1], w_r[2 * i + 1]);
            FMA2(A01, w0, hva.x);
            FMA2(A23, w0, hvb.x);
            FMA2(A01, w1, hva.y);
            FMA2(A23, w1, hvb.y);
        }
        // smem-weight half: k in [KR, 128), paired
#pragma unroll 8
        for (int pp = 0; pp < NSP; pp++) {
            float2 wv = *(const float2*)&Wp[((size_t)pp * G4 + g) * 2];
            ulonglong2 hva = *(const ulonglong2*)&hA[(KR + 2 * pp) * 2];
            ulonglong2 hvb = *(const ulonglong2*)&hB[(KR + 2 * pp) * 2];
            ull_t w0 = pack2(wv.x, wv.x);
            ull_t w1 = pack2(wv.y, wv.y);
            FMA2(A01, w0, hva.x);
            FMA2(A23, w0, hvb.x);
            FMA2(A01, w1, hva.y);
            FMA2(A23, w1, hvb.y);
        }

        float a0, a1, a2, a3;
        unpack2(A01, a0, a1);
        unpack2(A23, a2, a3);

        // activation (warp-uniform branch: gt constant per warp)
        float v0, v1, v2, v3;
        if (gt == 2) {
            v0 = tanhfast(a0); v1 = tanhfast(a1); v2 = tanhfast(a2); v3 = tanhfast(a3);
        } else {
            v0 = sigf(a0); v1 = sigf(a1); v2 = sigf(a2); v3 = sigf(a3);
        }
        gates_s[gt * 512 + 0 * 128 + gj] = v0;
        gates_s[gt * 512 + 1 * 128 + gj] = v1;
        gates_s[gt * 512 + 2 * 128 + gj] = v2;
        gates_s[gt * 512 + 3 * 128 + gj] = v3;
        __syncthreads();

        // owner update: (ob, oj)
        float gi = gates_s[0 * 512 + ob * 128 + oj];
        float gf = gates_s[1 * 512 + ob * 128 + oj];
        float gg = gates_s[2 * 512 + ob * 128 + oj];
        float go = gates_s[3 * 512 + ob * 128 + oj];
        c = gf * c + gi * gg;
        float hh = go * tanhfast(c);
        if (ob < 2) hA[oj * 2 + ob] = hh;
        else        hB[oj * 2 + (ob - 2)] = hh;
        h_own = hh;
        if (yh) {
            __nv_bfloat16 bh = __float2bfloat16(hh);
            __nv_bfloat16 bl = __float2bfloat16(hh - __bfloat162float(bh));
            size_t mi = ((size_t)(b0 + ob) * TT + t) * 256 + dir * 128 + oj;
            yh[mi] = bh;
            yl[mi] = bl;
        } else {
            y_f32[((size_t)(b0 + ob) * TT + t) * 256 + dir * 128 + oj] = hh;
        }
        __syncthreads();
    }

    // final states -> h_n / c_n rows (layer*2 + dir)
    int rowsel = layer * 2 + dir;
    hn_out[((size_t)rowsel * BB + (b0 + ob)) * HH + oj] = h_own;
    cn_out[((size_t)rowsel * BB + (b0 + ob)) * HH + oj] = c;
}

// ---------------- launcher ----------------
extern "C" void kernel_launch(void* const* d_in, const int* in_sizes, int n_in,
                              void* d_out, int out_size) {
    const float* x     = (const float*)d_in[0];
    const float* wih0f = (const float*)d_in[1];
    const float* whh0f = (const float*)d_in[2];
    const float* b0f   = (const float*)d_in[3];
    const float* wih0b = (const float*)d_in[4];
    const float* whh0b = (const float*)d_in[5];
    const float* b0b   = (const float*)d_in[6];
    const float* wih1f = (const float*)d_in[7];
    const float* whh1f = (const float*)d_in[8];
    const float* b1f   = (const float*)d_in[9];
    const float* wih1b = (const float*)d_in[10];
    const float* whh1b = (const float*)d_in[11];
    const float* b1b   = (const float*)d_in[12];

    float* out = (float*)d_out;
    float* y1  = out;                              // [256][512][256]
    float* hn  = out + (size_t)BB * TT * 256;      // [4][256][128]
    float* cn  = hn + 4 * BB * HH;                 // [4][256][128]

    __nv_bfloat16* ah_ptr;
    __nv_bfloat16* al_ptr;
    cudaGetSymbolAddress((void**)&ah_ptr, g_a_hi);
    cudaGetSymbolAddress((void**)&al_ptr, g_a_lo);

    cudaFuncSetAttribute(rec_kernel, cudaFuncAttributeMaxDynamicSharedMemorySize, REC_SMEM);
    cudaFuncSetAttribute(gx1_mma, cudaFuncAttributeMaxDynamicSharedMemorySize, GX1_SMEM);

    // 1. weight transposes + bf16 weight split
    prep_weights<<<512, 256>>>(whh0f, whh0b, whh1f, whh1b, wih0f, wih0b, wih1f, wih1b);
    // 2. layer-0 input projection
    gx0_kernel<<<(BB * TT) / 16, 512>>>(x, b0f, b0b);
    // 3. layer-0 recurrence -> bf16 hi/lo y0 + h_n/c_n rows 0,1
    rec_kernel<<<128, 512, REC_SMEM>>>(nullptr, ah_ptr, al_ptr, hn, cn, 0);
    // 4. layer-1 input projection: tcgen05 bf16-split GEMM
    {
        dim3 grid(4, (BB * TT) / 128);
        gx1_mma<<<grid, 128, GX1_SMEM>>>(b1f, b1b);
    }
    // 5. layer-1 recurrence -> y1 + h_n/c_n rows 2,3
    rec_kernel<<<128, 512, REC_SMEM>>>(y1, nullptr, nullptr, hn, cn, 1);
}